// round 7
// baseline (speedup 1.0000x reference)
#include <cuda_runtime.h>
#include <cuda_fp16.h>

#define HH   128
#define GG   512          // 4*H
#define TT   512
#define BB   512
#define KIN  18
#define KINP 20           // padded to mult of 4
#define BT   4            // batches per CTA
#define NBLK (BB / BT)

// static scratch (no allocation allowed in kernel_launch)
__device__ float g_h1[(size_t)BB * TT * HH];     // layer0 hidden, 128 MB
__device__ float g_xp1[(size_t)BB * TT * GG];    // layer1 input proj, 512 MB
__device__ float g_hlast[BB * HH];

__device__ __forceinline__ float sigf(float z) {
    return __fdividef(1.0f, 1.0f + __expf(-z));
}
__device__ __forceinline__ float tanh_f(float z) {
    return __fmaf_rn(2.0f, __fdividef(1.0f, 1.0f + __expf(-2.0f * z)), -1.0f);
}

struct __align__(16) SmemL0 {
    __half2 Whh[32 * GG][2];        // [kk][row]: 4 halfs (k=4kk..4kk+3)  131072 B
    float   Wih[KINP / 4][GG][4];   // zero-padded                        40960 B
    float   bias[GG];
    float   h[BT][HH];
    float   xbuf[2][BT][KINP];
    float   gates[GG * BT];         // [row][b]
};
struct __align__(16) SmemL1 {
    __half2 Whh[32 * GG][2];
    float   h[BT][HH];
    float   gates[GG * BT];
};

// ---------------- Layer 0: fused input proj (K=18) + recurrence ----------------
__global__ void __launch_bounds__(512, 1)
lstm_layer0(const float* __restrict__ x, const float* __restrict__ Wih,
            const float* __restrict__ Whh, const float* __restrict__ bih,
            const float* __restrict__ bhh)
{
    extern __shared__ char smem_raw[];
    SmemL0& s = *reinterpret_cast<SmemL0*>(smem_raw);
    const int tid = threadIdx.x;
    const int bb  = blockIdx.x * BT;

    // init A: zero pads, convert Whh->fp16, fold biases, zero h
    for (int i = tid; i < (KINP / 4) * GG * 4; i += 512)
        reinterpret_cast<float*>(s.Wih)[i] = 0.0f;
    for (int i = tid; i < 2 * BT * KINP; i += 512)
        (&s.xbuf[0][0][0])[i] = 0.0f;
    s.h[tid >> 7][tid & 127] = 0.0f;
    for (int i = tid; i < GG; i += 512) s.bias[i] = bih[i] + bhh[i];
    for (int i = tid; i < GG * HH; i += 512) {
        int row = i >> 7, k = i & 127;
        reinterpret_cast<__half*>(&s.Whh[(k >> 2) * GG + row][0])[k & 3] =
            __float2half(Whh[i]);
    }
    __syncthreads();
    // init B: real Wih entries + x(t=0)
    for (int i = tid; i < GG * KIN; i += 512) {
        int row = i / KIN, k = i - row * KIN;
        s.Wih[k >> 2][row][k & 3] = Wih[i];
    }
    const bool is_xthr = (tid < BT * KIN);
    const int  xb_ = is_xthr ? tid / KIN : 0;
    const int  xj  = is_xthr ? tid - (tid / KIN) * KIN : 0;
    if (is_xthr) s.xbuf[0][xb_][xj] = x[((size_t)(bb + xb_) * TT) * KIN + xj];
    __syncthreads();

    float c = 0.0f;
    const int u = tid & 127, b2 = tid >> 7;

    for (int t = 0; t < TT; ++t) {
        const int cur = t & 1, nxt = cur ^ 1;
        float xr = 0.0f;
        const bool pf = is_xthr && (t + 1 < TT);
        if (pf) xr = x[((size_t)(bb + xb_) * TT + (t + 1)) * KIN + xj];

        float a0 = s.bias[tid], a1 = a0, a2 = a0, a3 = a0;

        #pragma unroll
        for (int k4 = 0; k4 < KINP / 4; ++k4) {
            float4 w  = *reinterpret_cast<const float4*>(&s.Wih[k4][tid][0]);
            float4 x0 = *reinterpret_cast<const float4*>(&s.xbuf[cur][0][k4 * 4]);
            float4 x1 = *reinterpret_cast<const float4*>(&s.xbuf[cur][1][k4 * 4]);
            float4 x2 = *reinterpret_cast<const float4*>(&s.xbuf[cur][2][k4 * 4]);
            float4 x3 = *reinterpret_cast<const float4*>(&s.xbuf[cur][3][k4 * 4]);
            a0 = __fmaf_rn(w.x,x0.x,a0); a0 = __fmaf_rn(w.y,x0.y,a0);
            a0 = __fmaf_rn(w.z,x0.z,a0); a0 = __fmaf_rn(w.w,x0.w,a0);
            a1 = __fmaf_rn(w.x,x1.x,a1); a1 = __fmaf_rn(w.y,x1.y,a1);
            a1 = __fmaf_rn(w.z,x1.z,a1); a1 = __fmaf_rn(w.w,x1.w,a1);
            a2 = __fmaf_rn(w.x,x2.x,a2); a2 = __fmaf_rn(w.y,x2.y,a2);
            a2 = __fmaf_rn(w.z,x2.z,a2); a2 = __fmaf_rn(w.w,x2.w,a2);
            a3 = __fmaf_rn(w.x,x3.x,a3); a3 = __fmaf_rn(w.y,x3.y,a3);
            a3 = __fmaf_rn(w.z,x3.z,a3); a3 = __fmaf_rn(w.w,x3.w,a3);
        }
        #pragma unroll 8
        for (int kk = 0; kk < 32; ++kk) {
            float2 fa = __half22float2(s.Whh[kk * GG + tid][0]);
            float2 fb = __half22float2(s.Whh[kk * GG + tid][1]);
            float4 h0 = *reinterpret_cast<const float4*>(&s.h[0][kk * 4]);
            float4 h1 = *reinterpret_cast<const float4*>(&s.h[1][kk * 4]);
            float4 h2 = *reinterpret_cast<const float4*>(&s.h[2][kk * 4]);
            float4 h3 = *reinterpret_cast<const float4*>(&s.h[3][kk * 4]);
            a0 = __fmaf_rn(fa.x,h0.x,a0); a0 = __fmaf_rn(fa.y,h0.y,a0);
            a0 = __fmaf_rn(fb.x,h0.z,a0); a0 = __fmaf_rn(fb.y,h0.w,a0);
            a1 = __fmaf_rn(fa.x,h1.x,a1); a1 = __fmaf_rn(fa.y,h1.y,a1);
            a1 = __fmaf_rn(fb.x,h1.z,a1); a1 = __fmaf_rn(fb.y,h1.w,a1);
            a2 = __fmaf_rn(fa.x,h2.x,a2); a2 = __fmaf_rn(fa.y,h2.y,a2);
            a2 = __fmaf_rn(fb.x,h2.z,a2); a2 = __fmaf_rn(fb.y,h2.w,a2);
            a3 = __fmaf_rn(fa.x,h3.x,a3); a3 = __fmaf_rn(fa.y,h3.y,a3);
            a3 = __fmaf_rn(fb.x,h3.z,a3); a3 = __fmaf_rn(fb.y,h3.w,a3);
        }

        *reinterpret_cast<float4*>(&s.gates[tid * 4]) = make_float4(a0, a1, a2, a3);
        if (pf) s.xbuf[nxt][xb_][xj] = xr;
        __syncthreads();

        float zi = s.gates[(      u) * 4 + b2];
        float zf = s.gates[(128 + u) * 4 + b2];
        float zg = s.gates[(256 + u) * 4 + b2];
        float zo = s.gates[(384 + u) * 4 + b2];
        float ig = sigf(zi), fg = sigf(zf), gg = tanh_f(zg), og = sigf(zo);
        c = __fmaf_rn(fg, c, ig * gg);
        float hv = og * tanh_f(c);
        s.h[b2][u] = hv;
        g_h1[((size_t)(bb + b2) * TT + t) * HH + u] = hv;
        __syncthreads();
    }
}

// ------------- x_proj1 = h1 @ Wih1^T + bih1 + bhh1  (M=262144,N=512,K=128) -------------
__global__ void __launch_bounds__(256, 2)
xproj1_gemm(const float* __restrict__ Wih1, const float* __restrict__ bih1,
            const float* __restrict__ bhh1)
{
    extern __shared__ char smem_raw[];
    float* As = reinterpret_cast<float*>(smem_raw);  // [128][65]
    float* Bs = As + 128 * 65;                       // [128][65]
    const int tid = threadIdx.x;
    const int tn = tid & 15, tm = tid >> 4;
    const int mBase = blockIdx.y * 64, nBase = blockIdx.x * 64;

    for (int e = tid; e < 64 * 128; e += 256) {
        int r = e >> 7, k = e & 127;
        As[k * 65 + r] = g_h1[(size_t)(mBase + r) * HH + k];
        Bs[k * 65 + r] = Wih1[(nBase + r) * HH + k];
    }
    __syncthreads();

    float acc[4][4];
    #pragma unroll
    for (int i = 0; i < 4; ++i)
        #pragma unroll
        for (int j = 0; j < 4; ++j) acc[i][j] = 0.0f;

    #pragma unroll 4
    for (int k = 0; k < 128; ++k) {
        float av[4], bv[4];
        #pragma unroll
        for (int i = 0; i < 4; ++i) av[i] = As[k * 65 + tm * 4 + i];
        #pragma unroll
        for (int j = 0; j < 4; ++j) bv[j] = Bs[k * 65 + tn * 4 + j];
        #pragma unroll
        for (int i = 0; i < 4; ++i)
            #pragma unroll
            for (int j = 0; j < 4; ++j)
                acc[i][j] = __fmaf_rn(av[i], bv[j], acc[i][j]);
    }

    float bias[4];
    #pragma unroll
    for (int j = 0; j < 4; ++j) {
        int n = nBase + tn * 4 + j;
        bias[j] = bih1[n] + bhh1[n];
    }
    #pragma unroll
    for (int i = 0; i < 4; ++i) {
        size_t m = (size_t)(mBase + tm * 4 + i);
        float4 o = make_float4(acc[i][0] + bias[0], acc[i][1] + bias[1],
                               acc[i][2] + bias[2], acc[i][3] + bias[3]);
        *reinterpret_cast<float4*>(&g_xp1[m * GG + nBase + tn * 4]) = o;
    }
}

// ---------------- Layer 1 recurrence: xp1 (global) + h @ Whh1^T ----------------
__global__ void __launch_bounds__(512, 1)
lstm_layer1(const float* __restrict__ Whh)
{
    extern __shared__ char smem_raw[];
    SmemL1& s = *reinterpret_cast<SmemL1*>(smem_raw);
    const int tid = threadIdx.x;
    const int bb  = blockIdx.x * BT;

    s.h[tid >> 7][tid & 127] = 0.0f;
    for (int i = tid; i < GG * HH; i += 512) {
        int row = i >> 7, k = i & 127;
        reinterpret_cast<__half*>(&s.Whh[(k >> 2) * GG + row][0])[k & 3] =
            __float2half(Whh[i]);
    }
    __syncthreads();

    float c = 0.0f;
    const int u = tid & 127, b2 = tid >> 7;

    for (int t = 0; t < TT; ++t) {
        // independent global loads issue early; matmul hides the latency
        float xp0 = g_xp1[((size_t)(bb + 0) * TT + t) * GG + tid];
        float xp1 = g_xp1[((size_t)(bb + 1) * TT + t) * GG + tid];
        float xp2 = g_xp1[((size_t)(bb + 2) * TT + t) * GG + tid];
        float xp3 = g_xp1[((size_t)(bb + 3) * TT + t) * GG + tid];

        float a0 = 0.f, a1 = 0.f, a2 = 0.f, a3 = 0.f;
        #pragma unroll 8
        for (int kk = 0; kk < 32; ++kk) {
            float2 fa = __half22float2(s.Whh[kk * GG + tid][0]);
            float2 fb = __half22float2(s.Whh[kk * GG + tid][1]);
            float4 h0 = *reinterpret_cast<const float4*>(&s.h[0][kk * 4]);
            float4 h1 = *reinterpret_cast<const float4*>(&s.h[1][kk * 4]);
            float4 h2 = *reinterpret_cast<const float4*>(&s.h[2][kk * 4]);
            float4 h3 = *reinterpret_cast<const float4*>(&s.h[3][kk * 4]);
            a0 = __fmaf_rn(fa.x,h0.x,a0); a0 = __fmaf_rn(fa.y,h0.y,a0);
            a0 = __fmaf_rn(fb.x,h0.z,a0); a0 = __fmaf_rn(fb.y,h0.w,a0);
            a1 = __fmaf_rn(fa.x,h1.x,a1); a1 = __fmaf_rn(fa.y,h1.y,a1);
            a1 = __fmaf_rn(fb.x,h1.z,a1); a1 = __fmaf_rn(fb.y,h1.w,a1);
            a2 = __fmaf_rn(fa.x,h2.x,a2); a2 = __fmaf_rn(fa.y,h2.y,a2);
            a2 = __fmaf_rn(fb.x,h2.z,a2); a2 = __fmaf_rn(fb.y,h2.w,a2);
            a3 = __fmaf_rn(fa.x,h3.x,a3); a3 = __fmaf_rn(fa.y,h3.y,a3);
            a3 = __fmaf_rn(fb.x,h3.z,a3); a3 = __fmaf_rn(fb.y,h3.w,a3);
        }
        a0 += xp0; a1 += xp1; a2 += xp2; a3 += xp3;

        *reinterpret_cast<float4*>(&s.gates[tid * 4]) = make_float4(a0, a1, a2, a3);
        __syncthreads();

        float zi = s.gates[(      u) * 4 + b2];
        float zf = s.gates[(128 + u) * 4 + b2];
        float zg = s.gates[(256 + u) * 4 + b2];
        float zo = s.gates[(384 + u) * 4 + b2];
        float ig = sigf(zi), fg = sigf(zf), gg = tanh_f(zg), og = sigf(zo);
        c = __fmaf_rn(fg, c, ig * gg);
        float hv = og * tanh_f(c);
        s.h[b2][u] = hv;
        if (t == TT - 1) g_hlast[(bb + b2) * HH + u] = hv;
        __syncthreads();
    }
}

// ---------------- FC head: sigmoid(relu(h@W1^T+b1)@W2^T+b2) ----------------
__global__ void __launch_bounds__(64)
fc_head(const float* __restrict__ Wfc1, const float* __restrict__ bfc1,
        const float* __restrict__ Wfc2, const float* __restrict__ bfc2,
        float* __restrict__ out)
{
    __shared__ float red[2];
    const int b = blockIdx.x, j = threadIdx.x;
    const float* h = &g_hlast[b * HH];
    float acc = bfc1[j];
    #pragma unroll 8
    for (int k = 0; k < HH; ++k) acc = __fmaf_rn(h[k], Wfc1[j * HH + k], acc);
    float v = fmaxf(acc, 0.0f) * Wfc2[j];
    #pragma unroll
    for (int off = 16; off > 0; off >>= 1)
        v += __shfl_down_sync(0xFFFFFFFFu, v, off);
    if ((j & 31) == 0) red[j >> 5] = v;
    __syncthreads();
    if (j == 0) {
        float z = red[0] + red[1] + bfc2[0];
        out[b] = __fdividef(1.0f, 1.0f + __expf(-z));
    }
}

extern "C" void kernel_launch(void* const* d_in, const int* in_sizes, int n_in,
                              void* d_out, int out_size)
{
    const float* x     = (const float*)d_in[0];
    const float* Wih0  = (const float*)d_in[1];
    const float* Whh0  = (const float*)d_in[2];
    const float* bih0  = (const float*)d_in[3];
    const float* bhh0  = (const float*)d_in[4];
    const float* Wih1  = (const float*)d_in[5];
    const float* Whh1  = (const float*)d_in[6];
    const float* bih1  = (const float*)d_in[7];
    const float* bhh1  = (const float*)d_in[8];
    const float* Wfc1  = (const float*)d_in[9];
    const float* bfc1  = (const float*)d_in[10];
    const float* Wfc2  = (const float*)d_in[11];
    const float* bfc2  = (const float*)d_in[12];
    float* out = (float*)d_out;

    static bool attr_done = false;
    if (!attr_done) {
        cudaFuncSetAttribute(lstm_layer0, cudaFuncAttributeMaxDynamicSharedMemorySize,
                             (int)sizeof(SmemL0));
        cudaFuncSetAttribute(lstm_layer1, cudaFuncAttributeMaxDynamicSharedMemorySize,
                             (int)sizeof(SmemL1));
        cudaFuncSetAttribute(xproj1_gemm, cudaFuncAttributeMaxDynamicSharedMemorySize,
                             2 * 128 * 65 * (int)sizeof(float));
        attr_done = true;
    }

    lstm_layer0<<<NBLK, 512, sizeof(SmemL0)>>>(x, Wih0, Whh0, bih0, bhh0);
    {
        dim3 grid(GG / 64, (BB * TT) / 64);
        xproj1_gemm<<<grid, 256, 2 * 128 * 65 * sizeof(float)>>>(Wih1, bih1, bhh1);
    }
    lstm_layer1<<<NBLK, 512, sizeof(SmemL1)>>>(Whh1);
    fc_head<<<BB, 64>>>(Wfc1, bfc1, Wfc2, bfc2, out);
}

// round 8
// speedup vs baseline: 1.0773x; 1.0773x over previous
#include <cuda_runtime.h>
#include <cuda_fp16.h>

#define HH   128
#define GG   512          // 4*H
#define TT   512
#define BB   512
#define KIN  18
#define KINP 20           // padded to mult of 4
#define BT   4            // batches per CTA
#define NBLK (BB / BT)

typedef unsigned long long u64;

// static scratch (no allocation allowed in kernel_launch)
__device__ float g_h1[(size_t)BB * TT * HH];     // layer0 hidden, 128 MB
__device__ float g_xp1[(size_t)BB * TT * GG];    // layer1 input proj, 512 MB
__device__ float g_hlast[BB * HH];

// ---- packed fp32x2 helpers (SASS FFMA2; only reachable via PTX) ----
__device__ __forceinline__ u64 pack2(float lo, float hi) {
    u64 r; asm("mov.b64 %0, {%1, %2};" : "=l"(r) : "f"(lo), "f"(hi)); return r;
}
__device__ __forceinline__ float2 unpack2(u64 v) {
    float2 r; asm("mov.b64 {%0, %1}, %2;" : "=f"(r.x), "=f"(r.y) : "l"(v)); return r;
}
__device__ __forceinline__ void fma2(u64& d, u64 a, u64 b) {
    asm("fma.rn.f32x2 %0, %1, %2, %0;" : "+l"(d) : "l"(a), "l"(b));
}
__device__ __forceinline__ u64 h2f2(__half2 h) {
    float2 f = __half22float2(h);
    return pack2(f.x, f.y);
}

__device__ __forceinline__ float sigf(float z) {
    return __fdividef(1.0f, 1.0f + __expf(-z));
}
__device__ __forceinline__ float tanh_f(float z) {
    return __fmaf_rn(2.0f, __fdividef(1.0f, 1.0f + __expf(-2.0f * z)), -1.0f);
}

struct __align__(16) SmemL0 {
    __half2 Whh[32 * GG][2];        // [kk][row]: 4 halfs (k=4kk..4kk+3)  131072 B
    float   Wih[KINP / 4][GG][4];   // zero-padded                        40960 B
    float   bias[GG];
    float   h[BT][HH];
    float   xbuf[2][BT][KINP];
    float   gates[GG * BT];         // [row][b]
};
struct __align__(16) SmemL1 {
    __half2 Whh[32 * GG][2];
    float   h[BT][HH];
    float   gates[GG * BT];
};

// ---------------- Layer 0: fused input proj (K=18) + recurrence ----------------
__global__ void __launch_bounds__(512, 1)
lstm_layer0(const float* __restrict__ x, const float* __restrict__ Wih,
            const float* __restrict__ Whh, const float* __restrict__ bih,
            const float* __restrict__ bhh)
{
    extern __shared__ char smem_raw[];
    SmemL0& s = *reinterpret_cast<SmemL0*>(smem_raw);
    const int tid = threadIdx.x;
    const int bb  = blockIdx.x * BT;

    // init A: zero pads, convert Whh->fp16, fold biases, zero h
    for (int i = tid; i < (KINP / 4) * GG * 4; i += 512)
        reinterpret_cast<float*>(s.Wih)[i] = 0.0f;
    for (int i = tid; i < 2 * BT * KINP; i += 512)
        (&s.xbuf[0][0][0])[i] = 0.0f;
    s.h[tid >> 7][tid & 127] = 0.0f;
    for (int i = tid; i < GG; i += 512) s.bias[i] = bih[i] + bhh[i];
    for (int i = tid; i < GG * HH; i += 512) {
        int row = i >> 7, k = i & 127;
        reinterpret_cast<__half*>(&s.Whh[(k >> 2) * GG + row][0])[k & 3] =
            __float2half(Whh[i]);
    }
    __syncthreads();
    // init B: real Wih entries + x(t=0)
    for (int i = tid; i < GG * KIN; i += 512) {
        int row = i / KIN, k = i - row * KIN;
        s.Wih[k >> 2][row][k & 3] = Wih[i];
    }
    const bool is_xthr = (tid < BT * KIN);
    const int  xb_ = is_xthr ? tid / KIN : 0;
    const int  xj  = is_xthr ? tid - (tid / KIN) * KIN : 0;
    if (is_xthr) s.xbuf[0][xb_][xj] = x[((size_t)(bb + xb_) * TT) * KIN + xj];
    __syncthreads();

    float c = 0.0f;
    const int u = tid & 127, b2 = tid >> 7;

    for (int t = 0; t < TT; ++t) {
        const int cur = t & 1, nxt = cur ^ 1;
        float xr = 0.0f;
        const bool pf = is_xthr && (t + 1 < TT);
        if (pf) xr = x[((size_t)(bb + xb_) * TT + (t + 1)) * KIN + xj];

        // accumulator lanes = even/odd-k partial sums; bias in lane 0
        u64 A0 = pack2(s.bias[tid], 0.0f), A1 = A0, A2 = A0, A3 = A0;

        #pragma unroll
        for (int k4 = 0; k4 < KINP / 4; ++k4) {
            ulonglong2 w  = *reinterpret_cast<const ulonglong2*>(&s.Wih[k4][tid][0]);
            ulonglong2 x0 = *reinterpret_cast<const ulonglong2*>(&s.xbuf[cur][0][k4 * 4]);
            ulonglong2 x1 = *reinterpret_cast<const ulonglong2*>(&s.xbuf[cur][1][k4 * 4]);
            ulonglong2 x2 = *reinterpret_cast<const ulonglong2*>(&s.xbuf[cur][2][k4 * 4]);
            ulonglong2 x3 = *reinterpret_cast<const ulonglong2*>(&s.xbuf[cur][3][k4 * 4]);
            fma2(A0, w.x, x0.x); fma2(A0, w.y, x0.y);
            fma2(A1, w.x, x1.x); fma2(A1, w.y, x1.y);
            fma2(A2, w.x, x2.x); fma2(A2, w.y, x2.y);
            fma2(A3, w.x, x3.x); fma2(A3, w.y, x3.y);
        }
        #pragma unroll 8
        for (int kk = 0; kk < 32; ++kk) {
            u64 wa = h2f2(s.Whh[kk * GG + tid][0]);
            u64 wb = h2f2(s.Whh[kk * GG + tid][1]);
            ulonglong2 h0 = *reinterpret_cast<const ulonglong2*>(&s.h[0][kk * 4]);
            ulonglong2 h1 = *reinterpret_cast<const ulonglong2*>(&s.h[1][kk * 4]);
            ulonglong2 h2 = *reinterpret_cast<const ulonglong2*>(&s.h[2][kk * 4]);
            ulonglong2 h3 = *reinterpret_cast<const ulonglong2*>(&s.h[3][kk * 4]);
            fma2(A0, wa, h0.x); fma2(A0, wb, h0.y);
            fma2(A1, wa, h1.x); fma2(A1, wb, h1.y);
            fma2(A2, wa, h2.x); fma2(A2, wb, h2.y);
            fma2(A3, wa, h3.x); fma2(A3, wb, h3.y);
        }

        float2 r0 = unpack2(A0), r1 = unpack2(A1), r2 = unpack2(A2), r3 = unpack2(A3);
        *reinterpret_cast<float4*>(&s.gates[tid * 4]) =
            make_float4(r0.x + r0.y, r1.x + r1.y, r2.x + r2.y, r3.x + r3.y);
        if (pf) s.xbuf[nxt][xb_][xj] = xr;
        __syncthreads();

        float zi = s.gates[(      u) * 4 + b2];
        float zf = s.gates[(128 + u) * 4 + b2];
        float zg = s.gates[(256 + u) * 4 + b2];
        float zo = s.gates[(384 + u) * 4 + b2];
        float ig = sigf(zi), fg = sigf(zf), gg = tanh_f(zg), og = sigf(zo);
        c = __fmaf_rn(fg, c, ig * gg);
        float hv = og * tanh_f(c);
        s.h[b2][u] = hv;
        g_h1[((size_t)(bb + b2) * TT + t) * HH + u] = hv;
        __syncthreads();
    }
}

// ------------- x_proj1 = h1 @ Wih1^T + bih1 + bhh1  (M=262144,N=512,K=128) -------------
// f32x2 packed along n: acc lanes = (n even, n odd); no final lane reduction.
#define AS_STRIDE 65
#define BS_STRIDE 68
__global__ void __launch_bounds__(256, 2)
xproj1_gemm(const float* __restrict__ Wih1, const float* __restrict__ bih1,
            const float* __restrict__ bhh1)
{
    extern __shared__ char smem_raw[];
    float* As = reinterpret_cast<float*>(smem_raw);  // [128][65]  (k-major, m contiguous)
    float* Bs = As + 128 * AS_STRIDE;                // [128][68]  (k-major, n contiguous)
    const int tid = threadIdx.x;
    const int tn = tid & 15, tm = tid >> 4;
    const int mBase = blockIdx.y * 64, nBase = blockIdx.x * 64;

    for (int e = tid; e < 64 * 128; e += 256) {
        int r = e >> 7, k = e & 127;
        As[k * AS_STRIDE + r] = g_h1[(size_t)(mBase + r) * HH + k];
        Bs[k * BS_STRIDE + r] = Wih1[(nBase + r) * HH + k];
    }
    __syncthreads();

    u64 acc[4][2];
    {
        const int n0 = nBase + tn * 4;
        u64 b01 = pack2(bih1[n0 + 0] + bhh1[n0 + 0], bih1[n0 + 1] + bhh1[n0 + 1]);
        u64 b23 = pack2(bih1[n0 + 2] + bhh1[n0 + 2], bih1[n0 + 3] + bhh1[n0 + 3]);
        #pragma unroll
        for (int i = 0; i < 4; ++i) { acc[i][0] = b01; acc[i][1] = b23; }
    }

    #pragma unroll 8
    for (int k = 0; k < 128; ++k) {
        const float* ar = &As[k * AS_STRIDE + tm * 4];
        u64 d0 = pack2(ar[0], ar[0]);
        u64 d1 = pack2(ar[1], ar[1]);
        u64 d2 = pack2(ar[2], ar[2]);
        u64 d3 = pack2(ar[3], ar[3]);
        ulonglong2 bv = *reinterpret_cast<const ulonglong2*>(&Bs[k * BS_STRIDE + tn * 4]);
        fma2(acc[0][0], d0, bv.x); fma2(acc[0][1], d0, bv.y);
        fma2(acc[1][0], d1, bv.x); fma2(acc[1][1], d1, bv.y);
        fma2(acc[2][0], d2, bv.x); fma2(acc[2][1], d2, bv.y);
        fma2(acc[3][0], d3, bv.x); fma2(acc[3][1], d3, bv.y);
    }

    #pragma unroll
    for (int i = 0; i < 4; ++i) {
        size_t m = (size_t)(mBase + tm * 4 + i);
        ulonglong2 o; o.x = acc[i][0]; o.y = acc[i][1];
        *reinterpret_cast<ulonglong2*>(&g_xp1[m * GG + nBase + tn * 4]) = o;
    }
}

// ---------------- Layer 1 recurrence: xp1 (global) + h @ Whh1^T ----------------
__global__ void __launch_bounds__(512, 1)
lstm_layer1(const float* __restrict__ Whh)
{
    extern __shared__ char smem_raw[];
    SmemL1& s = *reinterpret_cast<SmemL1*>(smem_raw);
    const int tid = threadIdx.x;
    const int bb  = blockIdx.x * BT;

    s.h[tid >> 7][tid & 127] = 0.0f;
    for (int i = tid; i < GG * HH; i += 512) {
        int row = i >> 7, k = i & 127;
        reinterpret_cast<__half*>(&s.Whh[(k >> 2) * GG + row][0])[k & 3] =
            __float2half(Whh[i]);
    }
    __syncthreads();

    float c = 0.0f;
    const int u = tid & 127, b2 = tid >> 7;

    for (int t = 0; t < TT; ++t) {
        // independent global loads issue early; matmul hides the latency
        float xp0 = g_xp1[((size_t)(bb + 0) * TT + t) * GG + tid];
        float xp1 = g_xp1[((size_t)(bb + 1) * TT + t) * GG + tid];
        float xp2 = g_xp1[((size_t)(bb + 2) * TT + t) * GG + tid];
        float xp3 = g_xp1[((size_t)(bb + 3) * TT + t) * GG + tid];

        u64 A0 = pack2(xp0, 0.0f);
        u64 A1 = pack2(xp1, 0.0f);
        u64 A2 = pack2(xp2, 0.0f);
        u64 A3 = pack2(xp3, 0.0f);

        #pragma unroll 8
        for (int kk = 0; kk < 32; ++kk) {
            u64 wa = h2f2(s.Whh[kk * GG + tid][0]);
            u64 wb = h2f2(s.Whh[kk * GG + tid][1]);
            ulonglong2 h0 = *reinterpret_cast<const ulonglong2*>(&s.h[0][kk * 4]);
            ulonglong2 h1 = *reinterpret_cast<const ulonglong2*>(&s.h[1][kk * 4]);
            ulonglong2 h2 = *reinterpret_cast<const ulonglong2*>(&s.h[2][kk * 4]);
            ulonglong2 h3 = *reinterpret_cast<const ulonglong2*>(&s.h[3][kk * 4]);
            fma2(A0, wa, h0.x); fma2(A0, wb, h0.y);
            fma2(A1, wa, h1.x); fma2(A1, wb, h1.y);
            fma2(A2, wa, h2.x); fma2(A2, wb, h2.y);
            fma2(A3, wa, h3.x); fma2(A3, wb, h3.y);
        }

        float2 r0 = unpack2(A0), r1 = unpack2(A1), r2 = unpack2(A2), r3 = unpack2(A3);
        *reinterpret_cast<float4*>(&s.gates[tid * 4]) =
            make_float4(r0.x + r0.y, r1.x + r1.y, r2.x + r2.y, r3.x + r3.y);
        __syncthreads();

        float zi = s.gates[(      u) * 4 + b2];
        float zf = s.gates[(128 + u) * 4 + b2];
        float zg = s.gates[(256 + u) * 4 + b2];
        float zo = s.gates[(384 + u) * 4 + b2];
        float ig = sigf(zi), fg = sigf(zf), gg = tanh_f(zg), og = sigf(zo);
        c = __fmaf_rn(fg, c, ig * gg);
        float hv = og * tanh_f(c);
        s.h[b2][u] = hv;
        if (t == TT - 1) g_hlast[(bb + b2) * HH + u] = hv;
        __syncthreads();
    }
}

// ---------------- FC head: sigmoid(relu(h@W1^T+b1)@W2^T+b2) ----------------
__global__ void __launch_bounds__(64)
fc_head(const float* __restrict__ Wfc1, const float* __restrict__ bfc1,
        const float* __restrict__ Wfc2, const float* __restrict__ bfc2,
        float* __restrict__ out)
{
    __shared__ float red[2];
    const int b = blockIdx.x, j = threadIdx.x;
    const float* h = &g_hlast[b * HH];
    float acc = bfc1[j];
    #pragma unroll 8
    for (int k = 0; k < HH; ++k) acc = __fmaf_rn(h[k], Wfc1[j * HH + k], acc);
    float v = fmaxf(acc, 0.0f) * Wfc2[j];
    #pragma unroll
    for (int off = 16; off > 0; off >>= 1)
        v += __shfl_down_sync(0xFFFFFFFFu, v, off);
    if ((j & 31) == 0) red[j >> 5] = v;
    __syncthreads();
    if (j == 0) {
        float z = red[0] + red[1] + bfc2[0];
        out[b] = __fdividef(1.0f, 1.0f + __expf(-z));
    }
}

extern "C" void kernel_launch(void* const* d_in, const int* in_sizes, int n_in,
                              void* d_out, int out_size)
{
    const float* x     = (const float*)d_in[0];
    const float* Wih0  = (const float*)d_in[1];
    const float* Whh0  = (const float*)d_in[2];
    const float* bih0  = (const float*)d_in[3];
    const float* bhh0  = (const float*)d_in[4];
    const float* Wih1  = (const float*)d_in[5];
    const float* Whh1  = (const float*)d_in[6];
    const float* bih1  = (const float*)d_in[7];
    const float* bhh1  = (const float*)d_in[8];
    const float* Wfc1  = (const float*)d_in[9];
    const float* bfc1  = (const float*)d_in[10];
    const float* Wfc2  = (const float*)d_in[11];
    const float* bfc2  = (const float*)d_in[12];
    float* out = (float*)d_out;

    static bool attr_done = false;
    if (!attr_done) {
        cudaFuncSetAttribute(lstm_layer0, cudaFuncAttributeMaxDynamicSharedMemorySize,
                             (int)sizeof(SmemL0));
        cudaFuncSetAttribute(lstm_layer1, cudaFuncAttributeMaxDynamicSharedMemorySize,
                             (int)sizeof(SmemL1));
        cudaFuncSetAttribute(xproj1_gemm, cudaFuncAttributeMaxDynamicSharedMemorySize,
                             (128 * AS_STRIDE + 128 * BS_STRIDE) * (int)sizeof(float));
        attr_done = true;
    }

    lstm_layer0<<<NBLK, 512, sizeof(SmemL0)>>>(x, Wih0, Whh0, bih0, bhh0);
    {
        dim3 grid(GG / 64, (BB * TT) / 64);
        xproj1_gemm<<<grid, 256, (128 * AS_STRIDE + 128 * BS_STRIDE) * sizeof(float)>>>(
            Wih1, bih1, bhh1);
    }
    lstm_layer1<<<NBLK, 512, sizeof(SmemL1)>>>(Whh1);
    fc_head<<<BB, 64>>>(Wfc1, bfc1, Wfc2, bfc2, out);
}

// round 9
// speedup vs baseline: 1.1072x; 1.0278x over previous
#include <cuda_runtime.h>
#include <cuda_bf16.h>

#define HH   128
#define GG   512          // 4*H
#define TT   512
#define BB   512
#define KIN  18
#define KINP 20           // padded to mult of 4
#define BT   4            // batches per CTA
#define NBLK (BB / BT)

typedef unsigned long long u64;

// static scratch (no allocation allowed in kernel_launch)
__device__ float g_h1[(size_t)BB * TT * HH];     // layer0 hidden, 128 MB
__device__ float g_xp1[(size_t)BB * TT * GG];    // layer1 input proj, 512 MB

// ---- packed fp32x2 helpers (SASS FFMA2; only reachable via PTX) ----
__device__ __forceinline__ u64 pack2(float lo, float hi) {
    u64 r; asm("mov.b64 %0, {%1, %2};" : "=l"(r) : "f"(lo), "f"(hi)); return r;
}
__device__ __forceinline__ float2 unpack2(u64 v) {
    float2 r; asm("mov.b64 {%0, %1}, %2;" : "=f"(r.x), "=f"(r.y) : "l"(v)); return r;
}
__device__ __forceinline__ void fma2(u64& d, u64 a, u64 b) {
    asm("fma.rn.f32x2 %0, %1, %2, %0;" : "+l"(d) : "l"(a), "l"(b));
}
// two bf16 weights packed in one u32 -> f32x2 pair, pure ALU (no F2F)
__device__ __forceinline__ u64 bfpair(unsigned v) {
    unsigned lo = v << 16;
    unsigned hi = v & 0xFFFF0000u;
    u64 r; asm("mov.b64 %0, {%1, %2};" : "=l"(r) : "r"(lo), "r"(hi)); return r;
}
__device__ __forceinline__ unsigned bfpack(float w0, float w1) {
    unsigned a = (unsigned)__bfloat16_as_ushort(__float2bfloat16(w0));
    unsigned b = (unsigned)__bfloat16_as_ushort(__float2bfloat16(w1));
    return (b << 16) | a;
}

__device__ __forceinline__ float tanh_hw(float z) {
    float r; asm("tanh.approx.f32 %0, %1;" : "=f"(r) : "f"(z)); return r;
}
__device__ __forceinline__ float sig_hw(float z) {
    return __fmaf_rn(0.5f, tanh_hw(0.5f * z), 0.5f);
}
__device__ __forceinline__ float sig_exact(float z) {
    return __fdividef(1.0f, 1.0f + __expf(-z));
}

struct __align__(16) SmemL0 {
    uint2   Whh[32 * GG];           // [kk][row]: 4 bf16 (k=4kk..4kk+3)  131072 B
    float   Wih[KINP / 4][GG][4];   // zero-padded fp32                  40960 B
    float   bias[GG];
    float   h[BT][HH];
    float   xbuf[2][BT][KINP];
    float   gates[GG * BT];         // [row][b]
};
struct __align__(16) SmemL1 {
    uint2   Whh[32 * GG];
    float   h[BT][HH];
    float   gates[GG * BT];
    float   fcred[BT][2];
};

// ---------------- Layer 0: fused input proj (K=18) + recurrence ----------------
__global__ void __launch_bounds__(512, 1)
lstm_layer0(const float* __restrict__ x, const float* __restrict__ Wih,
            const float* __restrict__ Whh, const float* __restrict__ bih,
            const float* __restrict__ bhh)
{
    extern __shared__ char smem_raw[];
    SmemL0& s = *reinterpret_cast<SmemL0*>(smem_raw);
    const int tid = threadIdx.x;
    const int bb  = blockIdx.x * BT;

    // init A: zero pads, pack Whh->bf16-pairs, fold biases, zero h
    for (int i = tid; i < (KINP / 4) * GG * 4; i += 512)
        reinterpret_cast<float*>(s.Wih)[i] = 0.0f;
    for (int i = tid; i < 2 * BT * KINP; i += 512)
        (&s.xbuf[0][0][0])[i] = 0.0f;
    s.h[tid >> 7][tid & 127] = 0.0f;
    for (int i = tid; i < GG; i += 512) s.bias[i] = bih[i] + bhh[i];
    for (int i = tid; i < GG * 64; i += 512) {     // i indexes k-pairs
        int row = i >> 6, k2 = i & 63;             // k = 2*k2
        unsigned v = bfpack(Whh[row * HH + 2 * k2], Whh[row * HH + 2 * k2 + 1]);
        reinterpret_cast<unsigned*>(s.Whh)[((k2 >> 1) * GG + row) * 2 + (k2 & 1)] = v;
    }
    __syncthreads();
    // init B: real Wih entries + x(t=0)
    for (int i = tid; i < GG * KIN; i += 512) {
        int row = i / KIN, k = i - row * KIN;
        s.Wih[k >> 2][row][k & 3] = Wih[i];
    }
    const bool is_xthr = (tid < BT * KIN);
    const int  xb_ = is_xthr ? tid / KIN : 0;
    const int  xj  = is_xthr ? tid - (tid / KIN) * KIN : 0;
    if (is_xthr) s.xbuf[0][xb_][xj] = x[((size_t)(bb + xb_) * TT) * KIN + xj];
    __syncthreads();

    float c = 0.0f;
    const int u = tid & 127, b2 = tid >> 7;

    for (int t = 0; t < TT; ++t) {
        const int cur = t & 1, nxt = cur ^ 1;
        float xr = 0.0f;
        const bool pf = is_xthr && (t + 1 < TT);
        if (pf) xr = x[((size_t)(bb + xb_) * TT + (t + 1)) * KIN + xj];

        // accumulator lanes = even/odd-k partial sums; bias in lane 0
        u64 A0 = pack2(s.bias[tid], 0.0f), A1 = A0, A2 = A0, A3 = A0;

        #pragma unroll
        for (int k4 = 0; k4 < KINP / 4; ++k4) {
            ulonglong2 w  = *reinterpret_cast<const ulonglong2*>(&s.Wih[k4][tid][0]);
            ulonglong2 x0 = *reinterpret_cast<const ulonglong2*>(&s.xbuf[cur][0][k4 * 4]);
            ulonglong2 x1 = *reinterpret_cast<const ulonglong2*>(&s.xbuf[cur][1][k4 * 4]);
            ulonglong2 x2 = *reinterpret_cast<const ulonglong2*>(&s.xbuf[cur][2][k4 * 4]);
            ulonglong2 x3 = *reinterpret_cast<const ulonglong2*>(&s.xbuf[cur][3][k4 * 4]);
            fma2(A0, w.x, x0.x); fma2(A0, w.y, x0.y);
            fma2(A1, w.x, x1.x); fma2(A1, w.y, x1.y);
            fma2(A2, w.x, x2.x); fma2(A2, w.y, x2.y);
            fma2(A3, w.x, x3.x); fma2(A3, w.y, x3.y);
        }
        #pragma unroll 8
        for (int kk = 0; kk < 32; ++kk) {
            uint2 w = s.Whh[kk * GG + tid];
            u64 wa = bfpair(w.x);
            u64 wb = bfpair(w.y);
            ulonglong2 h0 = *reinterpret_cast<const ulonglong2*>(&s.h[0][kk * 4]);
            ulonglong2 h1 = *reinterpret_cast<const ulonglong2*>(&s.h[1][kk * 4]);
            ulonglong2 h2 = *reinterpret_cast<const ulonglong2*>(&s.h[2][kk * 4]);
            ulonglong2 h3 = *reinterpret_cast<const ulonglong2*>(&s.h[3][kk * 4]);
            fma2(A0, wa, h0.x); fma2(A0, wb, h0.y);
            fma2(A1, wa, h1.x); fma2(A1, wb, h1.y);
            fma2(A2, wa, h2.x); fma2(A2, wb, h2.y);
            fma2(A3, wa, h3.x); fma2(A3, wb, h3.y);
        }

        float2 r0 = unpack2(A0), r1 = unpack2(A1), r2 = unpack2(A2), r3 = unpack2(A3);
        *reinterpret_cast<float4*>(&s.gates[tid * 4]) =
            make_float4(r0.x + r0.y, r1.x + r1.y, r2.x + r2.y, r3.x + r3.y);
        if (pf) s.xbuf[nxt][xb_][xj] = xr;
        __syncthreads();

        float zi = s.gates[(      u) * 4 + b2];
        float zf = s.gates[(128 + u) * 4 + b2];
        float zg = s.gates[(256 + u) * 4 + b2];
        float zo = s.gates[(384 + u) * 4 + b2];
        float ig = sig_hw(zi), fg = sig_hw(zf), gg = tanh_hw(zg), og = sig_hw(zo);
        c = __fmaf_rn(fg, c, ig * gg);
        float hv = og * tanh_hw(c);
        s.h[b2][u] = hv;
        g_h1[((size_t)(bb + b2) * TT + t) * HH + u] = hv;
        __syncthreads();
    }
}

// ------------- x_proj1 = h1 @ Wih1^T + bih1 + bhh1  (M=262144,N=512,K=128) -------------
// f32x2 packed along n: acc lanes = (n even, n odd); no final lane reduction.
#define AS_STRIDE 65
#define BS_STRIDE 68
__global__ void __launch_bounds__(256, 2)
xproj1_gemm(const float* __restrict__ Wih1, const float* __restrict__ bih1,
            const float* __restrict__ bhh1)
{
    extern __shared__ char smem_raw[];
    float* As = reinterpret_cast<float*>(smem_raw);  // [128][65]  (k-major, m contiguous)
    float* Bs = As + 128 * AS_STRIDE;                // [128][68]  (k-major, n contiguous)
    const int tid = threadIdx.x;
    const int tn = tid & 15, tm = tid >> 4;
    const int mBase = blockIdx.y * 64, nBase = blockIdx.x * 64;

    for (int e = tid; e < 64 * 128; e += 256) {
        int r = e >> 7, k = e & 127;
        As[k * AS_STRIDE + r] = g_h1[(size_t)(mBase + r) * HH + k];
        Bs[k * BS_STRIDE + r] = Wih1[(nBase + r) * HH + k];
    }
    __syncthreads();

    u64 acc[4][2];
    {
        const int n0 = nBase + tn * 4;
        u64 b01 = pack2(bih1[n0 + 0] + bhh1[n0 + 0], bih1[n0 + 1] + bhh1[n0 + 1]);
        u64 b23 = pack2(bih1[n0 + 2] + bhh1[n0 + 2], bih1[n0 + 3] + bhh1[n0 + 3]);
        #pragma unroll
        for (int i = 0; i < 4; ++i) { acc[i][0] = b01; acc[i][1] = b23; }
    }

    #pragma unroll 8
    for (int k = 0; k < 128; ++k) {
        const float* ar = &As[k * AS_STRIDE + tm * 4];
        u64 d0 = pack2(ar[0], ar[0]);
        u64 d1 = pack2(ar[1], ar[1]);
        u64 d2 = pack2(ar[2], ar[2]);
        u64 d3 = pack2(ar[3], ar[3]);
        ulonglong2 bv = *reinterpret_cast<const ulonglong2*>(&Bs[k * BS_STRIDE + tn * 4]);
        fma2(acc[0][0], d0, bv.x); fma2(acc[0][1], d0, bv.y);
        fma2(acc[1][0], d1, bv.x); fma2(acc[1][1], d1, bv.y);
        fma2(acc[2][0], d2, bv.x); fma2(acc[2][1], d2, bv.y);
        fma2(acc[3][0], d3, bv.x); fma2(acc[3][1], d3, bv.y);
    }

    #pragma unroll
    for (int i = 0; i < 4; ++i) {
        size_t m = (size_t)(mBase + tm * 4 + i);
        ulonglong2 o; o.x = acc[i][0]; o.y = acc[i][1];
        *reinterpret_cast<ulonglong2*>(&g_xp1[m * GG + nBase + tn * 4]) = o;
    }
}

// ------- Layer 1 recurrence (xp1 + h @ Whh1^T), FC head fused at t = T-1 -------
__global__ void __launch_bounds__(512, 1)
lstm_layer1(const float* __restrict__ Whh,
            const float* __restrict__ Wfc1, const float* __restrict__ bfc1,
            const float* __restrict__ Wfc2, const float* __restrict__ bfc2,
            float* __restrict__ out)
{
    extern __shared__ char smem_raw[];
    SmemL1& s = *reinterpret_cast<SmemL1*>(smem_raw);
    const int tid = threadIdx.x;
    const int bb  = blockIdx.x * BT;

    s.h[tid >> 7][tid & 127] = 0.0f;
    for (int i = tid; i < GG * 64; i += 512) {
        int row = i >> 6, k2 = i & 63;
        unsigned v = bfpack(Whh[row * HH + 2 * k2], Whh[row * HH + 2 * k2 + 1]);
        reinterpret_cast<unsigned*>(s.Whh)[((k2 >> 1) * GG + row) * 2 + (k2 & 1)] = v;
    }
    __syncthreads();

    float c = 0.0f;
    const int u = tid & 127, b2 = tid >> 7;

    for (int t = 0; t < TT; ++t) {
        // independent global loads issue early; matmul hides the latency
        float xp0 = g_xp1[((size_t)(bb + 0) * TT + t) * GG + tid];
        float xp1 = g_xp1[((size_t)(bb + 1) * TT + t) * GG + tid];
        float xp2 = g_xp1[((size_t)(bb + 2) * TT + t) * GG + tid];
        float xp3 = g_xp1[((size_t)(bb + 3) * TT + t) * GG + tid];

        u64 A0 = pack2(xp0, 0.0f);
        u64 A1 = pack2(xp1, 0.0f);
        u64 A2 = pack2(xp2, 0.0f);
        u64 A3 = pack2(xp3, 0.0f);

        #pragma unroll 8
        for (int kk = 0; kk < 32; ++kk) {
            uint2 w = s.Whh[kk * GG + tid];
            u64 wa = bfpair(w.x);
            u64 wb = bfpair(w.y);
            ulonglong2 h0 = *reinterpret_cast<const ulonglong2*>(&s.h[0][kk * 4]);
            ulonglong2 h1 = *reinterpret_cast<const ulonglong2*>(&s.h[1][kk * 4]);
            ulonglong2 h2 = *reinterpret_cast<const ulonglong2*>(&s.h[2][kk * 4]);
            ulonglong2 h3 = *reinterpret_cast<const ulonglong2*>(&s.h[3][kk * 4]);
            fma2(A0, wa, h0.x); fma2(A0, wb, h0.y);
            fma2(A1, wa, h1.x); fma2(A1, wb, h1.y);
            fma2(A2, wa, h2.x); fma2(A2, wb, h2.y);
            fma2(A3, wa, h3.x); fma2(A3, wb, h3.y);
        }

        float2 r0 = unpack2(A0), r1 = unpack2(A1), r2 = unpack2(A2), r3 = unpack2(A3);
        *reinterpret_cast<float4*>(&s.gates[tid * 4]) =
            make_float4(r0.x + r0.y, r1.x + r1.y, r2.x + r2.y, r3.x + r3.y);
        __syncthreads();

        float zi = s.gates[(      u) * 4 + b2];
        float zf = s.gates[(128 + u) * 4 + b2];
        float zg = s.gates[(256 + u) * 4 + b2];
        float zo = s.gates[(384 + u) * 4 + b2];
        float ig = sig_hw(zi), fg = sig_hw(zf), gg = tanh_hw(zg), og = sig_hw(zo);
        c = __fmaf_rn(fg, c, ig * gg);
        float hv = og * tanh_hw(c);
        s.h[b2][u] = hv;
        __syncthreads();
    }

    // ---- fused FC head on the final h (exact math; sets final rel_err) ----
    // 256 threads: bl = tid>>6 (batch 0..3), j = tid&63 (hidden unit of fc1)
    if (tid < 256) {
        const int bl = tid >> 6, j = tid & 63;
        float acc = bfc1[j];
        const float* wr = &Wfc1[j * HH];
        #pragma unroll 8
        for (int k = 0; k < HH; ++k) acc = __fmaf_rn(s.h[bl][k], wr[k], acc);
        float v = fmaxf(acc, 0.0f) * Wfc2[j];
        #pragma unroll
        for (int off = 16; off > 0; off >>= 1)
            v += __shfl_down_sync(0xFFFFFFFFu, v, off);
        if ((j & 31) == 0) s.fcred[bl][j >> 5] = v;
    }
    __syncthreads();
    if (tid < BT) {
        float z = s.fcred[tid][0] + s.fcred[tid][1] + bfc2[0];
        out[bb + tid] = sig_exact(z);
    }
}

extern "C" void kernel_launch(void* const* d_in, const int* in_sizes, int n_in,
                              void* d_out, int out_size)
{
    const float* x     = (const float*)d_in[0];
    const float* Wih0  = (const float*)d_in[1];
    const float* Whh0  = (const float*)d_in[2];
    const float* bih0  = (const float*)d_in[3];
    const float* bhh0  = (const float*)d_in[4];
    const float* Wih1  = (const float*)d_in[5];
    const float* Whh1  = (const float*)d_in[6];
    const float* bih1  = (const float*)d_in[7];
    const float* bhh1  = (const float*)d_in[8];
    const float* Wfc1  = (const float*)d_in[9];
    const float* bfc1  = (const float*)d_in[10];
    const float* Wfc2  = (const float*)d_in[11];
    const float* bfc2  = (const float*)d_in[12];
    float* out = (float*)d_out;

    static bool attr_done = false;
    if (!attr_done) {
        cudaFuncSetAttribute(lstm_layer0, cudaFuncAttributeMaxDynamicSharedMemorySize,
                             (int)sizeof(SmemL0));
        cudaFuncSetAttribute(lstm_layer1, cudaFuncAttributeMaxDynamicSharedMemorySize,
                             (int)sizeof(SmemL1));
        cudaFuncSetAttribute(xproj1_gemm, cudaFuncAttributeMaxDynamicSharedMemorySize,
                             (128 * AS_STRIDE + 128 * BS_STRIDE) * (int)sizeof(float));
        attr_done = true;
    }

    lstm_layer0<<<NBLK, 512, sizeof(SmemL0)>>>(x, Wih0, Whh0, bih0, bhh0);
    {
        dim3 grid(GG / 64, (BB * TT) / 64);
        xproj1_gemm<<<grid, 256, (128 * AS_STRIDE + 128 * BS_STRIDE) * sizeof(float)>>>(
            Wih1, bih1, bhh1);
    }
    lstm_layer1<<<NBLK, 512, sizeof(SmemL1)>>>(Whh1, Wfc1, bfc1, Wfc2, bfc2, out);
}

// round 10
// speedup vs baseline: 1.4014x; 1.2657x over previous
#include <cuda_runtime.h>
#include <cuda_bf16.h>

#define HH   128
#define GG   512          // 4*H
#define TT   512
#define BB   512
#define KIN  18
#define BT   4            // batches per CTA
#define NBLK (BB / BT)

#define ZLEN   160        // unified z stride per batch (L0: 128 h + 32 x/pad; L1: 4*(32+8pad))
#define NJ0    10         // j-chunks per slice, layer0 (40 real k's)
#define NJ1    8          // j-chunks per slice, layer1 (32 real k's)
#define W0_E4  (NJ0 * 2)  // uint4 weight entries per thread, layer0
#define W1_E4  (NJ1 * 2)

typedef unsigned long long u64;

// static scratch (no allocation allowed in kernel_launch)
__device__ float g_h1[(size_t)BB * TT * HH];     // layer0 hidden
__device__ float g_xp1[(size_t)BB * TT * GG];    // layer1 input proj

// ---- packed fp32x2 helpers (SASS FFMA2; only reachable via PTX) ----
__device__ __forceinline__ u64 pack2(float lo, float hi) {
    u64 r; asm("mov.b64 %0, {%1, %2};" : "=l"(r) : "f"(lo), "f"(hi)); return r;
}
__device__ __forceinline__ float2 unpack2(u64 v) {
    float2 r; asm("mov.b64 {%0, %1}, %2;" : "=f"(r.x), "=f"(r.y) : "l"(v)); return r;
}
__device__ __forceinline__ void fma2(u64& d, u64 a, u64 b) {
    asm("fma.rn.f32x2 %0, %1, %2, %0;" : "+l"(d) : "l"(a), "l"(b));
}
// two bf16 weights packed in one u32 -> f32x2 pair, pure ALU (no F2F)
__device__ __forceinline__ u64 bfpair(unsigned v) {
    unsigned lo = v << 16;
    unsigned hi = v & 0xFFFF0000u;
    u64 r; asm("mov.b64 %0, {%1, %2};" : "=l"(r) : "r"(lo), "r"(hi)); return r;
}

__device__ __forceinline__ float tanh_hw(float z) {
    float r; asm("tanh.approx.f32 %0, %1;" : "=f"(r) : "f"(z)); return r;
}
__device__ __forceinline__ float sig_hw(float z) {
    return __fmaf_rn(0.5f, tanh_hw(0.5f * z), 0.5f);
}
__device__ __forceinline__ float sig_exact(float z) {
    return __fdividef(1.0f, 1.0f + __expf(-z));
}
__device__ __forceinline__ float sel4(float v0, float v1, float v2, float v3, int ks) {
    float a = (ks & 1) ? v1 : v0;
    float b = (ks & 1) ? v3 : v2;
    return (ks & 2) ? b : a;
}

// write one bf16 weight into the lane-private stream layout w4[e4][512]
// thread t2 = u*4+ks; entry e4 = j*2 + (g>>1); u32 slot = (g&1)*2 + (pos>>1); half = pos&1
__device__ __forceinline__ void emit_w(char* wbase, int row, int z, int slice_len, float val) {
    int g = row >> 7, u = row & 127;
    int ks = z / slice_len, jr = z - ks * slice_len;
    int j = jr >> 2, pos = jr & 3;
    int t2 = u * 4 + ks;
    int e4 = j * 2 + (g >> 1);
    size_t byte = ((size_t)(e4 * 512 + t2)) * 16 + (((g & 1) << 1) | (pos >> 1)) * 4 + (pos & 1) * 2;
    *reinterpret_cast<__nv_bfloat16*>(wbase + byte) = __float2bfloat16(val);
}

// 32-FFMA2 inner chunk shared by both layers (macro keeps everything in registers)
#define MM_CHUNK(wptr, zptr, jj)                                                   \
    {                                                                              \
        uint4 wA = (wptr)[((jj) * 2 + 0) * 512 + tid];                             \
        uint4 wB = (wptr)[((jj) * 2 + 1) * 512 + tid];                             \
        const float* zb = (zptr) + (jj) * 4;                                       \
        ulonglong2 z0 = *reinterpret_cast<const ulonglong2*>(zb);                  \
        ulonglong2 z1 = *reinterpret_cast<const ulonglong2*>(zb + ZLEN);           \
        ulonglong2 z2 = *reinterpret_cast<const ulonglong2*>(zb + 2 * ZLEN);       \
        ulonglong2 z3 = *reinterpret_cast<const ulonglong2*>(zb + 3 * ZLEN);       \
        u64 wg0a = bfpair(wA.x), wg0b = bfpair(wA.y);                              \
        u64 wg1a = bfpair(wA.z), wg1b = bfpair(wA.w);                              \
        u64 wg2a = bfpair(wB.x), wg2b = bfpair(wB.y);                              \
        u64 wg3a = bfpair(wB.z), wg3b = bfpair(wB.w);                              \
        fma2(acc[0][0], wg0a, z0.x); fma2(acc[0][0], wg0b, z0.y);                  \
        fma2(acc[0][1], wg0a, z1.x); fma2(acc[0][1], wg0b, z1.y);                  \
        fma2(acc[0][2], wg0a, z2.x); fma2(acc[0][2], wg0b, z2.y);                  \
        fma2(acc[0][3], wg0a, z3.x); fma2(acc[0][3], wg0b, z3.y);                  \
        fma2(acc[1][0], wg1a, z0.x); fma2(acc[1][0], wg1b, z0.y);                  \
        fma2(acc[1][1], wg1a, z1.x); fma2(acc[1][1], wg1b, z1.y);                  \
        fma2(acc[1][2], wg1a, z2.x); fma2(acc[1][2], wg1b, z2.y);                  \
        fma2(acc[1][3], wg1a, z3.x); fma2(acc[1][3], wg1b, z3.y);                  \
        fma2(acc[2][0], wg2a, z0.x); fma2(acc[2][0], wg2b, z0.y);                  \
        fma2(acc[2][1], wg2a, z1.x); fma2(acc[2][1], wg2b, z1.y);                  \
        fma2(acc[2][2], wg2a, z2.x); fma2(acc[2][2], wg2b, z2.y);                  \
        fma2(acc[2][3], wg2a, z3.x); fma2(acc[2][3], wg2b, z3.y);                  \
        fma2(acc[3][0], wg3a, z0.x); fma2(acc[3][0], wg3b, z0.y);                  \
        fma2(acc[3][1], wg3a, z1.x); fma2(acc[3][1], wg3b, z1.y);                  \
        fma2(acc[3][2], wg3a, z2.x); fma2(acc[3][2], wg3b, z2.y);                  \
        fma2(acc[3][3], wg3a, z3.x); fma2(acc[3][3], wg3b, z3.y);                  \
    }

// fold f32x2 lanes, butterfly over the 4 ks lanes, leaving full sums in g[][]
#define REDUCE_ACCS()                                                              \
    float gv[4][4];                                                                \
    _Pragma("unroll")                                                              \
    for (int gi = 0; gi < 4; ++gi)                                                 \
        _Pragma("unroll")                                                          \
        for (int bi = 0; bi < 4; ++bi) {                                           \
            float2 f = unpack2(acc[gi][bi]);                                       \
            float v = f.x + f.y;                                                   \
            v += __shfl_xor_sync(0xFFFFFFFFu, v, 1);                               \
            v += __shfl_xor_sync(0xFFFFFFFFu, v, 2);                               \
            gv[gi][bi] = v;                                                        \
        }

struct __align__(16) SmemL0 {
    uint4 w[W0_E4 * 512];           // 163840 B
    float z[2][BT][ZLEN];           // 5120 B
};
struct __align__(16) SmemL1 {
    uint4 w[W1_E4 * 512];           // 131072 B
    float z[2][BT][ZLEN];           // 5120 B
    float xp[2][BT][GG];            // 16384 B
    float fcred[BT][2];
};

// ---------------- Layer 0: fused input proj + recurrence ----------------
__global__ void __launch_bounds__(512, 1)
lstm_layer0(const float* __restrict__ x, const float* __restrict__ Wih,
            const float* __restrict__ Whh, const float* __restrict__ bih,
            const float* __restrict__ bhh)
{
    extern __shared__ char smem_raw[];
    SmemL0& s = *reinterpret_cast<SmemL0*>(smem_raw);
    const int tid = threadIdx.x;
    const int bb  = blockIdx.x * BT;
    const int u   = tid >> 2, ks = tid & 3;

    // ---- init: zero weight stream + z, scatter-pack weights ----
    for (int i = tid; i < W0_E4 * 512; i += 512) s.w[i] = make_uint4(0, 0, 0, 0);
    for (int i = tid; i < 2 * BT * ZLEN; i += 512) (&s.z[0][0][0])[i] = 0.0f;
    __syncthreads();
    for (int i = tid; i < GG * HH; i += 512)
        emit_w((char*)s.w, i >> 7, i & 127, 40, Whh[i]);
    for (int i = tid; i < GG * KIN; i += 512) {
        int row = i / KIN, k = i - row * KIN;
        emit_w((char*)s.w, row, 128 + k, 40, Wih[i]);
    }
    // biases for this thread's 4 gate rows (batch-independent)
    float bias_g[4];
    #pragma unroll
    for (int gi = 0; gi < 4; ++gi)
        bias_g[gi] = bih[gi * 128 + u] + bhh[gi * 128 + u];
    // stage x(0) into z[0]
    const bool is_xthr = (tid < BT * KIN);
    const int  xb_ = is_xthr ? tid / KIN : 0;
    const int  xj  = is_xthr ? tid - (tid / KIN) * KIN : 0;
    if (is_xthr) s.z[0][xb_][128 + xj] = x[((size_t)(bb + xb_) * TT) * KIN + xj];
    __syncthreads();

    float c = 0.0f;
    const int wu = tid & 127, wb = tid >> 7;   // writeback mapping (coalesced)

    for (int t = 0; t < TT; ++t) {
        const int cur = t & 1, nxt = cur ^ 1;
        float xr = 0.0f;
        const bool pf = is_xthr && (t + 1 < TT);
        if (pf) xr = x[((size_t)(bb + xb_) * TT + (t + 1)) * KIN + xj];

        // coalesced writeback of h(t-1) (lives in z[cur])
        if (t > 0)
            g_h1[((size_t)(bb + wb) * TT + (t - 1)) * HH + wu] = s.z[cur][wb][wu];

        u64 acc[4][4];
        #pragma unroll
        for (int gi = 0; gi < 4; ++gi)
            #pragma unroll
            for (int bi = 0; bi < 4; ++bi) acc[gi][bi] = 0ull;

        const float* zbase = &s.z[cur][0][ks * 40];
        #pragma unroll
        for (int j = 0; j < NJ0; ++j) MM_CHUNK(s.w, zbase, j);

        REDUCE_ACCS();

        float zi = sel4(gv[0][0], gv[0][1], gv[0][2], gv[0][3], ks) + bias_g[0];
        float zf = sel4(gv[1][0], gv[1][1], gv[1][2], gv[1][3], ks) + bias_g[1];
        float zg = sel4(gv[2][0], gv[2][1], gv[2][2], gv[2][3], ks) + bias_g[2];
        float zo = sel4(gv[3][0], gv[3][1], gv[3][2], gv[3][3], ks) + bias_g[3];
        float ig = sig_hw(zi), fg = sig_hw(zf), cg = tanh_hw(zg), og = sig_hw(zo);
        c = __fmaf_rn(fg, c, ig * cg);
        float hv = og * tanh_hw(c);

        s.z[nxt][ks][u] = hv;                  // this thread owns (u, batch=ks)
        if (pf) s.z[nxt][xb_][128 + xj] = xr;
        __syncthreads();
    }
    // final h(T-1) lives in z[TT & 1 ^ 1 ... = z[0]]
    g_h1[((size_t)(bb + wb) * TT + (TT - 1)) * HH + wu] = s.z[TT & 1][wb][wu];
}

// ------------- x_proj1 = h1 @ Wih1^T + bih1 + bhh1  (M=262144,N=512,K=128) -------------
#define AS_STRIDE 65
#define BS_STRIDE 68
__global__ void __launch_bounds__(256, 2)
xproj1_gemm(const float* __restrict__ Wih1, const float* __restrict__ bih1,
            const float* __restrict__ bhh1)
{
    extern __shared__ char smem_raw[];
    float* As = reinterpret_cast<float*>(smem_raw);  // [128][65]
    float* Bs = As + 128 * AS_STRIDE;                // [128][68]
    const int tid = threadIdx.x;
    const int tn = tid & 15, tm = tid >> 4;
    const int mBase = blockIdx.y * 64, nBase = blockIdx.x * 64;

    for (int e = tid; e < 64 * 128; e += 256) {
        int r = e >> 7, k = e & 127;
        As[k * AS_STRIDE + r] = g_h1[(size_t)(mBase + r) * HH + k];
        Bs[k * BS_STRIDE + r] = Wih1[(nBase + r) * HH + k];
    }
    __syncthreads();

    u64 acc[4][2];
    {
        const int n0 = nBase + tn * 4;
        u64 b01 = pack2(bih1[n0 + 0] + bhh1[n0 + 0], bih1[n0 + 1] + bhh1[n0 + 1]);
        u64 b23 = pack2(bih1[n0 + 2] + bhh1[n0 + 2], bih1[n0 + 3] + bhh1[n0 + 3]);
        #pragma unroll
        for (int i = 0; i < 4; ++i) { acc[i][0] = b01; acc[i][1] = b23; }
    }

    #pragma unroll 8
    for (int k = 0; k < 128; ++k) {
        const float* ar = &As[k * AS_STRIDE + tm * 4];
        u64 d0 = pack2(ar[0], ar[0]);
        u64 d1 = pack2(ar[1], ar[1]);
        u64 d2 = pack2(ar[2], ar[2]);
        u64 d3 = pack2(ar[3], ar[3]);
        ulonglong2 bv = *reinterpret_cast<const ulonglong2*>(&Bs[k * BS_STRIDE + tn * 4]);
        fma2(acc[0][0], d0, bv.x); fma2(acc[0][1], d0, bv.y);
        fma2(acc[1][0], d1, bv.x); fma2(acc[1][1], d1, bv.y);
        fma2(acc[2][0], d2, bv.x); fma2(acc[2][1], d2, bv.y);
        fma2(acc[3][0], d3, bv.x); fma2(acc[3][1], d3, bv.y);
    }

    #pragma unroll
    for (int i = 0; i < 4; ++i) {
        size_t m = (size_t)(mBase + tm * 4 + i);
        ulonglong2 o; o.x = acc[i][0]; o.y = acc[i][1];
        *reinterpret_cast<ulonglong2*>(&g_xp1[m * GG + nBase + tn * 4]) = o;
    }
}

// ------- Layer 1 recurrence (xp1 + h @ Whh1^T), FC head fused at the end -------
__global__ void __launch_bounds__(512, 1)
lstm_layer1(const float* __restrict__ Whh,
            const float* __restrict__ Wfc1, const float* __restrict__ bfc1,
            const float* __restrict__ Wfc2, const float* __restrict__ bfc2,
            float* __restrict__ out)
{
    extern __shared__ char smem_raw[];
    SmemL1& s = *reinterpret_cast<SmemL1*>(smem_raw);
    const int tid = threadIdx.x;
    const int bb  = blockIdx.x * BT;
    const int u   = tid >> 2, ks = tid & 3;

    for (int i = tid; i < W1_E4 * 512; i += 512) s.w[i] = make_uint4(0, 0, 0, 0);
    for (int i = tid; i < 2 * BT * ZLEN; i += 512) (&s.z[0][0][0])[i] = 0.0f;
    __syncthreads();
    for (int i = tid; i < GG * HH; i += 512)
        emit_w((char*)s.w, i >> 7, i & 127, 32, Whh[i]);
    // stage xp(0)
    const int xb = tid >> 7, xr4 = (tid & 127) * 4;
    {
        float4 v = *reinterpret_cast<const float4*>(
            &g_xp1[((size_t)(bb + xb) * TT + 0) * GG + xr4]);
        *reinterpret_cast<float4*>(&s.xp[0][xb][xr4]) = v;
    }
    __syncthreads();

    float c = 0.0f;

    for (int t = 0; t < TT; ++t) {
        const int cur = t & 1, nxt = cur ^ 1;
        float4 xpn = make_float4(0.f, 0.f, 0.f, 0.f);
        const bool pf = (t + 1 < TT);
        if (pf) xpn = *reinterpret_cast<const float4*>(
            &g_xp1[((size_t)(bb + xb) * TT + (t + 1)) * GG + xr4]);

        u64 acc[4][4];
        #pragma unroll
        for (int gi = 0; gi < 4; ++gi)
            #pragma unroll
            for (int bi = 0; bi < 4; ++bi) acc[gi][bi] = 0ull;

        const float* zbase = &s.z[cur][0][ks * 40];
        #pragma unroll
        for (int j = 0; j < NJ1; ++j) MM_CHUNK(s.w, zbase, j);

        if (pf) *reinterpret_cast<float4*>(&s.xp[nxt][xb][xr4]) = xpn;

        REDUCE_ACCS();

        const float* xpc = &s.xp[cur][ks][0];
        float zi = sel4(gv[0][0], gv[0][1], gv[0][2], gv[0][3], ks) + xpc[      u];
        float zf = sel4(gv[1][0], gv[1][1], gv[1][2], gv[1][3], ks) + xpc[128 + u];
        float zg = sel4(gv[2][0], gv[2][1], gv[2][2], gv[2][3], ks) + xpc[256 + u];
        float zo = sel4(gv[3][0], gv[3][1], gv[3][2], gv[3][3], ks) + xpc[384 + u];
        float ig = sig_hw(zi), fg = sig_hw(zf), cg = tanh_hw(zg), og = sig_hw(zo);
        c = __fmaf_rn(fg, c, ig * cg);
        float hv = og * tanh_hw(c);

        s.z[nxt][ks][(u >> 5) * 40 + (u & 31)] = hv;   // padded slice layout
        __syncthreads();
    }

    // ---- fused FC head on final h (in z[TT & 1]); exact math ----
    const int fin = TT & 1;
    if (tid < 256) {
        const int bl = tid >> 6, j = tid & 63;
        float accf = bfc1[j];
        const float* wr = &Wfc1[j * HH];
        #pragma unroll 8
        for (int k = 0; k < HH; ++k)
            accf = __fmaf_rn(s.z[fin][bl][(k >> 5) * 40 + (k & 31)], wr[k], accf);
        float v = fmaxf(accf, 0.0f) * Wfc2[j];
        #pragma unroll
        for (int off = 16; off > 0; off >>= 1)
            v += __shfl_down_sync(0xFFFFFFFFu, v, off);
        if ((j & 31) == 0) s.fcred[bl][j >> 5] = v;
    }
    __syncthreads();
    if (tid < BT) {
        float z = s.fcred[tid][0] + s.fcred[tid][1] + bfc2[0];
        out[bb + tid] = sig_exact(z);
    }
}

extern "C" void kernel_launch(void* const* d_in, const int* in_sizes, int n_in,
                              void* d_out, int out_size)
{
    const float* x     = (const float*)d_in[0];
    const float* Wih0  = (const float*)d_in[1];
    const float* Whh0  = (const float*)d_in[2];
    const float* bih0  = (const float*)d_in[3];
    const float* bhh0  = (const float*)d_in[4];
    const float* Wih1  = (const float*)d_in[5];
    const float* Whh1  = (const float*)d_in[6];
    const float* bih1  = (const float*)d_in[7];
    const float* bhh1  = (const float*)d_in[8];
    const float* Wfc1  = (const float*)d_in[9];
    const float* bfc1  = (const float*)d_in[10];
    const float* Wfc2  = (const float*)d_in[11];
    const float* bfc2  = (const float*)d_in[12];
    float* out = (float*)d_out;

    static bool attr_done = false;
    if (!attr_done) {
        cudaFuncSetAttribute(lstm_layer0, cudaFuncAttributeMaxDynamicSharedMemorySize,
                             (int)sizeof(SmemL0));
        cudaFuncSetAttribute(lstm_layer1, cudaFuncAttributeMaxDynamicSharedMemorySize,
                             (int)sizeof(SmemL1));
        cudaFuncSetAttribute(xproj1_gemm, cudaFuncAttributeMaxDynamicSharedMemorySize,
                             (128 * AS_STRIDE + 128 * BS_STRIDE) * (int)sizeof(float));
        attr_done = true;
    }

    lstm_layer0<<<NBLK, 512, sizeof(SmemL0)>>>(x, Wih0, Whh0, bih0, bhh0);
    {
        dim3 grid(GG / 64, (BB * TT) / 64);
        xproj1_gemm<<<grid, 256, (128 * AS_STRIDE + 128 * BS_STRIDE) * sizeof(float)>>>(
            Wih1, bih1, bhh1);
    }
    lstm_layer1<<<NBLK, 512, sizeof(SmemL1)>>>(Whh1, Wfc1, bfc1, Wfc2, bfc2, out);
}